// round 10
// baseline (speedup 1.0000x reference)
#include <cuda_runtime.h>
#include <math.h>

#define NN 10000
#define NE 40000
#define NG 128
#define VC 1584   // 32*48 kernel cols + 48 bias cols

// ---------------- scratch (static device globals; no runtime alloc) ----------
__device__ float g_a[NN * 32];
__device__ float g_e[NE * 32];
__device__ float g_s[NG * 16];
__device__ float g_v[NN * VC];      // 63.4 MB
__device__ float g_vs[NG * VC];     // 811 KB, per-graph state part of v
__device__ float g_wt[48 * VC];     // transposed kernel+bias
__device__ float g_agg[NN * 48];
__device__ float g_asum[NG * 32];
__device__ float g_esum[NG * 32];
__device__ float g_wcat1[32 * 192]; // [We rows 0:32 | We rows 32:64]
__device__ float g_wcat2[32 * 192]; // [We rows 80:112 | Ue]
__device__ float g_pa[NN * 192];    // a @ wcat1
__device__ float g_ew[NE * 192];    // e @ wcat2
__device__ float g_s3[NG * 96];     // s @ We rows 64:80
__device__ float g_agw[NN * 96];    // agg @ Wn
__device__ float g_au[NN * 96];     // a @ Un
__device__ int   g_rowp[NN + 1];    // CSR row offsets by src (pair is sorted)

__device__ __forceinline__ float sigm(float x) { return 1.f / (1.f + expf(-x)); }

__device__ __forceinline__ unsigned f2tf(float f) {
    unsigned u;
    asm("cvt.rna.tf32.f32 %0, %1;" : "=r"(u) : "f"(f));
    return u;
}
__device__ __forceinline__ void mma_tf32(float c[4],
                                         unsigned a0, unsigned a1,
                                         unsigned a2, unsigned a3,
                                         unsigned b0, unsigned b1) {
    asm volatile(
        "mma.sync.aligned.m16n8k8.row.col.f32.tf32.tf32.f32 "
        "{%0,%1,%2,%3}, {%4,%5,%6,%7}, {%8,%9}, {%0,%1,%2,%3};"
        : "+f"(c[0]), "+f"(c[1]), "+f"(c[2]), "+f"(c[3])
        : "r"(a0), "r"(a1), "r"(a2), "r"(a3), "r"(b0), "r"(b1));
}

// ---------------- weight prep ------------------------------------------------
__global__ void build_weights_kernel(const float* __restrict__ kern,
                                     const float* __restrict__ bias,
                                     const float* __restrict__ We,
                                     const float* __restrict__ Ue,
                                     float* __restrict__ wt,
                                     float* __restrict__ wcat1,
                                     float* __restrict__ wcat2) {
    int idx = blockIdx.x * blockDim.x + threadIdx.x;
    if (idx < 48 * VC) {
        int j = idx / VC, ki = idx % VC;
        wt[idx] = (ki < 1536) ? kern[ki * 48 + j] : bias[(ki - 1536) * 48 + j];
    }
    if (idx < 32 * 192) {
        int k = idx / 192, c = idx % 192;
        wcat1[idx] = (c < 96) ? We[k * 96 + c] : We[(32 + k) * 96 + (c - 96)];
        wcat2[idx] = (c < 96) ? We[(80 + k) * 96 + c] : Ue[k * 96 + (c - 96)];
    }
}

// ---------------- CSR row offsets (once; pair is constant) -------------------
__global__ void row_ptr_kernel(const int* __restrict__ pair,
                               int* __restrict__ rowp) {
    int n = blockIdx.x * blockDim.x + threadIdx.x;
    if (n > NN) return;
    int lo = 0, hi = NE;
    while (lo < hi) {
        int mid = (lo + hi) >> 1;
        if (pair[2 * mid] < n) lo = mid + 1; else hi = mid;
    }
    rowp[n] = lo;
}

// ---------------- zero small scratch -----------------------------------------
__global__ void zero_small_kernel(float* __restrict__ as, float* __restrict__ es) {
    int i = blockIdx.x * blockDim.x + threadIdx.x;
    if (i < NG * 32) { as[i] = 0.f; es[i] = 0.f; }
}

// ---------------- small-K dense GEMM: Y(MxNC) = X(MxK) @ W(KxNC) -------------
template<int K, int NC, int RT>
__global__ __launch_bounds__(NC)
void gemm_kernel(const float* __restrict__ X, const float* __restrict__ W,
                 float* __restrict__ Y, int M) {
    __shared__ float sW[K * NC];
    __shared__ __align__(16) float sx[RT * K];
    int tid = threadIdx.x;
    int base = blockIdx.x * RT;
#pragma unroll
    for (int k = 0; k < K; k++) sW[k * NC + tid] = W[k * NC + tid];
    int lim = (M - base) * K;
    for (int i = tid; i < RT * K; i += NC)
        sx[i] = (i < lim) ? X[(size_t)base * K + i] : 0.f;
    __syncthreads();

    float acc[RT];
#pragma unroll
    for (int r = 0; r < RT; r++) acc[r] = 0.f;
    const float4* sx4 = (const float4*)sx;
#pragma unroll
    for (int k4 = 0; k4 < K / 4; k4++) {
        float w0 = sW[(4 * k4 + 0) * NC + tid];
        float w1 = sW[(4 * k4 + 1) * NC + tid];
        float w2 = sW[(4 * k4 + 2) * NC + tid];
        float w3 = sW[(4 * k4 + 3) * NC + tid];
#pragma unroll
        for (int r = 0; r < RT; r++) {
            float4 xv = sx4[r * (K / 4) + k4];
            acc[r] += w0 * xv.x; acc[r] += w1 * xv.y;
            acc[r] += w2 * xv.z; acc[r] += w3 * xv.w;
        }
    }
#pragma unroll
    for (int r = 0; r < RT; r++) {
        int row = base + r;
        if (row < M) Y[(size_t)row * NC + tid] = acc[r];
    }
}

// ---------------- tf32 MMA GEMM: Y(Mx192) = X(Mx32) @ W(32x192) --------------
// 256 thr = 8 warps (4m x 2n); block tile 64 x 192; warp tile 16 x 96.
__global__ __launch_bounds__(256)
void gemm_mma_k32_n192(const float* __restrict__ X, const float* __restrict__ W,
                       float* __restrict__ Y, int M) {
    __shared__ unsigned sA[64 * 33];
    __shared__ unsigned sB[32 * 196];
    int m0 = blockIdx.x * 64;
    int tid = threadIdx.x;

    for (int i = tid; i < 64 * 32; i += 256) {
        int r = i >> 5, k = i & 31;
        float val = (m0 + r < M) ? X[(size_t)(m0 + r) * 32 + k] : 0.f;
        sA[r * 33 + k] = f2tf(val);
    }
    for (int i = tid; i < 32 * 192; i += 256) {
        int k = i / 192, n = i % 192;
        sB[k * 196 + n] = f2tf(W[k * 192 + n]);
    }
    __syncthreads();

    int wid = tid >> 5, lane = tid & 31;
    int wm = wid & 3, wn = wid >> 2;
    int lq = lane >> 2, lr = lane & 3;

    float c[12][4];
#pragma unroll
    for (int nf = 0; nf < 12; nf++)
#pragma unroll
        for (int i = 0; i < 4; i++) c[nf][i] = 0.f;

#pragma unroll
    for (int ks = 0; ks < 4; ks++) {
        int ar = wm * 16 + lq;
        int ac = ks * 8 + lr;
        unsigned a0 = sA[ar * 33 + ac];
        unsigned a1 = sA[(ar + 8) * 33 + ac];
        unsigned a2 = sA[ar * 33 + ac + 4];
        unsigned a3 = sA[(ar + 8) * 33 + ac + 4];
#pragma unroll
        for (int nf = 0; nf < 12; nf++) {
            int bn = wn * 96 + nf * 8 + lq;
            unsigned b0 = sB[(ks * 8 + lr) * 196 + bn];
            unsigned b1 = sB[(ks * 8 + 4 + lr) * 196 + bn];
            mma_tf32(c[nf], a0, a1, a2, a3, b0, b1);
        }
    }

    int row_l = wm * 16 + lq;
    int r0 = m0 + row_l, r1 = r0 + 8;
    int cb = wn * 96 + lr * 2;
#pragma unroll
    for (int nf = 0; nf < 12; nf++) {
        int col = cb + nf * 8;
        if (r0 < M) *(float2*)&Y[(size_t)r0 * 192 + col] = make_float2(c[nf][0], c[nf][1]);
        if (r1 < M) *(float2*)&Y[(size_t)r1 * 192 + col] = make_float2(c[nf][2], c[nf][3]);
    }
}

// ---------------- edge GRU finalize (pure elementwise) -----------------------
__global__ __launch_bounds__(256)
void edge_finalize_kernel(const float* __restrict__ pa,
                          const float* __restrict__ ew,
                          const float* __restrict__ s3,
                          const float* __restrict__ e_in,
                          const int* __restrict__ pair,
                          const int* __restrict__ bgi,
                          const float* __restrict__ bin,
                          const float* __restrict__ brec,
                          float* __restrict__ e_out,
                          float* __restrict__ esum) {
    int idx = blockIdx.x * blockDim.x + threadIdx.x;
    if (idx >= NE * 32) return;
    int e = idx >> 5, j = idx & 31;
    int src = pair[2 * e], dst = pair[2 * e + 1], g = bgi[e];
    const float* pA = pa + (size_t)src * 192;
    const float* pB = pa + (size_t)dst * 192 + 96;
    const float* pS = s3 + g * 96;
    const float* pE = ew + (size_t)e * 192;
    float xz = pA[j]      + pB[j]      + pS[j]      + pE[j]      + bin[j];
    float xr = pA[32 + j] + pB[32 + j] + pS[32 + j] + pE[32 + j] + bin[32 + j];
    float xh = pA[64 + j] + pB[64 + j] + pS[64 + j] + pE[64 + j] + bin[64 + j];
    float hz = pE[96 + j]  + brec[j];
    float hr = pE[128 + j] + brec[32 + j];
    float hh = pE[160 + j] + brec[64 + j];
    float h  = e_in[(size_t)e * 32 + j];
    float z  = sigm(xz + hz);
    float r  = sigm(xr + hr);
    float hc = tanhf(xh + r * hh);
    float val = z * h + (1.f - z) * hc;
    e_out[(size_t)e * 32 + j] = val;
    atomicAdd(&esum[g * 32 + j], val);
}

// ---------------- node GRU finalize ------------------------------------------
__global__ __launch_bounds__(256)
void node_finalize_kernel(const float* __restrict__ agw,
                          const float* __restrict__ au,
                          const float* __restrict__ a_in,
                          const int* __restrict__ agi,
                          const float* __restrict__ bin,
                          const float* __restrict__ brec,
                          float* __restrict__ a_out,
                          float* __restrict__ asum) {
    int idx = blockIdx.x * blockDim.x + threadIdx.x;
    if (idx >= NN * 32) return;
    int n = idx >> 5, j = idx & 31;
    const float* pX = agw + (size_t)n * 96;
    const float* pH = au  + (size_t)n * 96;
    float xz = pX[j]      + bin[j];
    float xr = pX[32 + j] + bin[32 + j];
    float xh = pX[64 + j] + bin[64 + j];
    float hz = pH[j]      + brec[j];
    float hr = pH[32 + j] + brec[32 + j];
    float hh = pH[64 + j] + brec[64 + j];
    float h  = a_in[(size_t)n * 32 + j];
    float z  = sigm(xz + hz);
    float r  = sigm(xr + hr);
    float hc = tanhf(xh + r * hh);
    float val = z * h + (1.f - z) * hc;
    a_out[(size_t)n * 32 + j] = val;
    atomicAdd(&asum[agi[n] * 32 + j], val);
}

// ---------------- vs[g][c] = sum_j wt[32+j][c] * s[g][j]  (state part) -------
__global__ __launch_bounds__(256)
void vs_kernel(const float* __restrict__ s, const float* __restrict__ wt,
               float* __restrict__ vs) {
    __shared__ float ss[16];
    int g = blockIdx.y;
    int c = blockIdx.x * 256 + threadIdx.x;
    if (threadIdx.x < 16) ss[threadIdx.x] = s[g * 16 + threadIdx.x];
    __syncthreads();
    if (c >= VC) return;
    float acc = 0.f;
#pragma unroll
    for (int j = 0; j < 16; j++) acc += ss[j] * wt[(32 + j) * VC + c];
    vs[(size_t)g * VC + c] = acc;
}

// ---------------- v = a @ Wt_a (tf32 tensor cores) + vs[agi] gather ----------
__global__ __launch_bounds__(256)
void compute_v_mma_kernel(const float* __restrict__ a,
                          const int* __restrict__ agi,
                          const float* __restrict__ wt,
                          const float* __restrict__ vs,
                          float* __restrict__ v) {
    __shared__ unsigned sA[64 * 33];
    __shared__ unsigned sB[32 * 132];
    __shared__ int s_gi[64];
    int m0 = blockIdx.y * 64;
    int n0 = blockIdx.x * 128;
    int tid = threadIdx.x;

    for (int i = tid; i < 64 * 32; i += 256) {
        int r = i >> 5, k = i & 31;
        float val = (m0 + r < NN) ? a[(size_t)(m0 + r) * 32 + k] : 0.f;
        sA[r * 33 + k] = f2tf(val);
    }
    for (int i = tid; i < 32 * 128; i += 256) {
        int k = i >> 7, n = i & 127;
        float val = (n0 + n < VC) ? wt[(size_t)k * VC + n0 + n] : 0.f;
        sB[k * 132 + n] = f2tf(val);
    }
    if (tid < 64) s_gi[tid] = (m0 + tid < NN) ? agi[m0 + tid] : 0;
    __syncthreads();

    int wid = tid >> 5, lane = tid & 31;
    int wm = wid & 3, wn = wid >> 2;
    int lq = lane >> 2, lr = lane & 3;

    float c[8][4];
#pragma unroll
    for (int nf = 0; nf < 8; nf++)
#pragma unroll
        for (int i = 0; i < 4; i++) c[nf][i] = 0.f;

#pragma unroll
    for (int ks = 0; ks < 4; ks++) {
        int ar = wm * 16 + lq;
        int ac = ks * 8 + lr;
        unsigned a0 = sA[ar * 33 + ac];
        unsigned a1 = sA[(ar + 8) * 33 + ac];
        unsigned a2 = sA[ar * 33 + ac + 4];
        unsigned a3 = sA[(ar + 8) * 33 + ac + 4];
#pragma unroll
        for (int nf = 0; nf < 8; nf++) {
            int bn = wn * 64 + nf * 8 + lq;
            unsigned b0 = sB[(ks * 8 + lr) * 132 + bn];
            unsigned b1 = sB[(ks * 8 + 4 + lr) * 132 + bn];
            mma_tf32(c[nf], a0, a1, a2, a3, b0, b1);
        }
    }

    int row_l = wm * 16 + lq;
    int r0 = m0 + row_l, r1 = r0 + 8;
    int gi0 = s_gi[row_l], gi1 = s_gi[row_l + 8];
    int cb = n0 + wn * 64 + lr * 2;
#pragma unroll
    for (int nf = 0; nf < 8; nf++) {
        int col = cb + nf * 8;
        if (col >= VC) continue;
        if (r0 < NN) {
            float2 w = *(const float2*)&vs[(size_t)gi0 * VC + col];
            *(float2*)&v[(size_t)r0 * VC + col] =
                make_float2(c[nf][0] + w.x, c[nf][1] + w.y);
        }
        if (r1 < NN) {
            float2 w = *(const float2*)&vs[(size_t)gi1 * VC + col];
            *(float2*)&v[(size_t)r1 * VC + col] =
                make_float2(c[nf][2] + w.x, c[nf][3] + w.y);
        }
    }
}

// ---------------- CSR scatter: one warp per src node, 2-edge ILP -------------
__global__ __launch_bounds__(256)
void scatter_csr_kernel(const float* __restrict__ e_feat,
                        const int* __restrict__ pair,
                        const int* __restrict__ rowp,
                        const float* __restrict__ v,
                        float* __restrict__ agg) {
    int lane = threadIdx.x & 31;
    int node = (blockIdx.x * blockDim.x + threadIdx.x) >> 5;
    if (node >= NN) return;
    int e = rowp[node], eend = rowp[node + 1];

    float accA0 = 0.f, accA1 = 0.f;   // stream A (48 cols: lane + lane<16)
    float accB0 = 0.f, accB1 = 0.f;   // stream B

    for (; e + 1 < eend; e += 2) {
        int dst0 = __ldg(&pair[2 * e + 1]);
        int dst1 = __ldg(&pair[2 * e + 3]);
        const float* vp0 = v + (size_t)dst0 * VC;
        const float* vp1 = v + (size_t)dst1 * VC;
        float ev0 = __ldg(&e_feat[(size_t)e * 32 + lane]);
        float ev1 = __ldg(&e_feat[(size_t)(e + 1) * 32 + lane]);
        accA0 += __ldg(&vp0[1536 + lane]);
        accB0 += __ldg(&vp1[1536 + lane]);
        if (lane < 16) {
            accA1 += __ldg(&vp0[1568 + lane]);
            accB1 += __ldg(&vp1[1568 + lane]);
        }
#pragma unroll
        for (int k = 0; k < 32; k++) {
            float ek0 = __shfl_sync(0xffffffffu, ev0, k);
            float ek1 = __shfl_sync(0xffffffffu, ev1, k);
            accA0 += ek0 * __ldg(&vp0[k * 48 + lane]);
            accB0 += ek1 * __ldg(&vp1[k * 48 + lane]);
            if (lane < 16) {
                accA1 += ek0 * __ldg(&vp0[k * 48 + 32 + lane]);
                accB1 += ek1 * __ldg(&vp1[k * 48 + 32 + lane]);
            }
        }
    }
    if (e < eend) {
        int dst0 = __ldg(&pair[2 * e + 1]);
        const float* vp0 = v + (size_t)dst0 * VC;
        float ev0 = __ldg(&e_feat[(size_t)e * 32 + lane]);
        accA0 += __ldg(&vp0[1536 + lane]);
        if (lane < 16) accA1 += __ldg(&vp0[1568 + lane]);
#pragma unroll
        for (int k = 0; k < 32; k++) {
            float ek0 = __shfl_sync(0xffffffffu, ev0, k);
            accA0 += ek0 * __ldg(&vp0[k * 48 + lane]);
            if (lane < 16) accA1 += ek0 * __ldg(&vp0[k * 48 + 32 + lane]);
        }
    }
    agg[(size_t)node * 48 + lane] = accA0 + accB0;
    if (lane < 16) agg[(size_t)node * 48 + 32 + lane] = accA1 + accB1;
}

// ---------------- state GRU: s = GRU([asum, esum, s], s) ---------------------
__global__ void state_gru_kernel(
    const float* __restrict__ asum, const float* __restrict__ esum,
    const float* __restrict__ s_in,
    const float* __restrict__ Ws, const float* __restrict__ Us,
    const float* __restrict__ bsin, const float* __restrict__ bsrec,
    float* __restrict__ s_out) {
    __shared__ float sx[80];
    __shared__ float shh[16];
    __shared__ float sxw[48];
    __shared__ float shu[48];
    int g = blockIdx.x;
    int c = threadIdx.x;  // 80
    if (c < 32)      sx[c] = asum[g * 32 + c];
    else if (c < 64) sx[c] = esum[g * 32 + (c - 32)];
    else             sx[c] = s_in[g * 16 + (c - 64)];
    if (c < 16) shh[c] = s_in[g * 16 + c];
    __syncthreads();
    if (c < 48) {
        float xw = bsin[c], hu = bsrec[c];
        for (int k = 0; k < 80; k++) xw += sx[k] * Ws[k * 48 + c];
        for (int k = 0; k < 16; k++) hu += shh[k] * Us[k * 48 + c];
        sxw[c] = xw; shu[c] = hu;
    }
    __syncthreads();
    if (c < 16) {
        float z = sigm(sxw[c] + shu[c]);
        float r = sigm(sxw[16 + c] + shu[16 + c]);
        float hc = tanhf(sxw[32 + c] + r * shu[32 + c]);
        s_out[g * 16 + c] = z * shh[c] + (1.f - z) * hc;
    }
}

// ---------------- host orchestration -----------------------------------------
extern "C" void kernel_launch(void* const* d_in, const int* in_sizes, int n_in,
                              void* d_out, int out_size) {
    const float* a0    = (const float*)d_in[0];
    const float* e0    = (const float*)d_in[1];
    const float* s0    = (const float*)d_in[2];
    const int*   pair  = (const int*)d_in[3];
    const int*   agi   = (const int*)d_in[4];
    const int*   bgi   = (const int*)d_in[5];
    const float* kern  = (const float*)d_in[6];
    const float* bias  = (const float*)d_in[7];
    const float* We    = (const float*)d_in[8];
    const float* Ue    = (const float*)d_in[9];
    const float* bein  = (const float*)d_in[10];
    const float* berec = (const float*)d_in[11];
    const float* Wn    = (const float*)d_in[12];
    const float* Un    = (const float*)d_in[13];
    const float* bnin  = (const float*)d_in[14];
    const float* bnrec = (const float*)d_in[15];
    const float* Ws    = (const float*)d_in[16];
    const float* Us    = (const float*)d_in[17];
    const float* bsin  = (const float*)d_in[18];
    const float* bsrec = (const float*)d_in[19];
    float* out = (float*)d_out;

    float *ga, *ge, *gs, *gv, *gvs, *gwt, *gagg, *gas, *ges;
    float *gw1, *gw2, *gpa, *gew, *gs3, *gagw, *gau;
    int *growp;
    cudaGetSymbolAddress((void**)&ga,    g_a);
    cudaGetSymbolAddress((void**)&ge,    g_e);
    cudaGetSymbolAddress((void**)&gs,    g_s);
    cudaGetSymbolAddress((void**)&gv,    g_v);
    cudaGetSymbolAddress((void**)&gvs,   g_vs);
    cudaGetSymbolAddress((void**)&gwt,   g_wt);
    cudaGetSymbolAddress((void**)&gagg,  g_agg);
    cudaGetSymbolAddress((void**)&gas,   g_asum);
    cudaGetSymbolAddress((void**)&ges,   g_esum);
    cudaGetSymbolAddress((void**)&gw1,   g_wcat1);
    cudaGetSymbolAddress((void**)&gw2,   g_wcat2);
    cudaGetSymbolAddress((void**)&gpa,   g_pa);
    cudaGetSymbolAddress((void**)&gew,   g_ew);
    cudaGetSymbolAddress((void**)&gs3,   g_s3);
    cudaGetSymbolAddress((void**)&gagw,  g_agw);
    cudaGetSymbolAddress((void**)&gau,   g_au);
    cudaGetSymbolAddress((void**)&growp, g_rowp);

    static bool s_init = false;
    static cudaStream_t st1, st2;
    static cudaEvent_t ev0[2], evZ[2], evP[2], evE[2], evU[2];
    if (!s_init) {
        cudaStreamCreateWithFlags(&st1, cudaStreamNonBlocking);
        cudaStreamCreateWithFlags(&st2, cudaStreamNonBlocking);
        for (int i = 0; i < 2; i++) {
            cudaEventCreateWithFlags(&ev0[i], cudaEventDisableTiming);
            cudaEventCreateWithFlags(&evZ[i], cudaEventDisableTiming);
            cudaEventCreateWithFlags(&evP[i], cudaEventDisableTiming);
            cudaEventCreateWithFlags(&evE[i], cudaEventDisableTiming);
            cudaEventCreateWithFlags(&evU[i], cudaEventDisableTiming);
        }
        s_init = true;
    }

    build_weights_kernel<<<(48 * VC + 255) / 256, 256>>>(kern, bias, We, Ue,
                                                         gwt, gw1, gw2);
    row_ptr_kernel<<<(NN + 256) / 256, 256>>>(pair, growp);

    float* oa[2] = {ga, out};
    float* oe[2] = {ge, out + NN * 32};
    float* os[2] = {gs, out + NN * 32 + NE * 32};
    const float* ia = a0;
    const float* ie = e0;
    const float* is_ = s0;

    for (int step = 0; step < 2; step++) {
        cudaEventRecord(ev0[step], 0);

        // main stream: vs then tf32 v-GEMM
        vs_kernel<<<dim3((VC + 255) / 256, NG), 256>>>(is_, gwt, gvs);
        compute_v_mma_kernel<<<dim3((VC + 127) / 128, (NN + 63) / 64), 256>>>(
            ia, agi, gwt, gvs, gv);

        // stream 2: zero asum/esum, pa GEMM, Un GEMM
        cudaStreamWaitEvent(st2, ev0[step], 0);
        zero_small_kernel<<<16, 256, 0, st2>>>(gas, ges);
        cudaEventRecord(evZ[step], st2);
        gemm_kernel<32, 192, 16><<<NN / 16, 192, 0, st2>>>(ia, gw1, gpa, NN);
        cudaEventRecord(evP[step], st2);
        gemm_kernel<32, 96, 16><<<NN / 16, 96, 0, st2>>>(ia, Un, gau, NN);
        cudaEventRecord(evU[step], st2);

        // stream 1: ew (tf32 MMA) + s3 GEMMs, then finalize
        cudaStreamWaitEvent(st1, ev0[step], 0);
        gemm_mma_k32_n192<<<NE / 64, 256, 0, st1>>>(ie, gw2, gew, NE);
        gemm_kernel<16, 96, 16><<<NG / 16, 96, 0, st1>>>(is_, We + 64 * 96, gs3, NG);
        cudaStreamWaitEvent(st1, evZ[step], 0);
        cudaStreamWaitEvent(st1, evP[step], 0);
        edge_finalize_kernel<<<(NE * 32 + 255) / 256, 256, 0, st1>>>(
            gpa, gew, gs3, ie, pair, bgi, bein, berec, oe[step], ges);
        cudaEventRecord(evE[step], st1);

        // join on main: CSR scatter needs v (main) + e_out (st1)
        cudaStreamWaitEvent(0, evE[step], 0);
        scatter_csr_kernel<<<(NN + 7) / 8, 256>>>(oe[step], pair, growp, gv, gagg);

        gemm_kernel<48, 96, 16><<<NN / 16, 96>>>(gagg, Wn, gagw, NN);
        cudaStreamWaitEvent(0, evU[step], 0);
        node_finalize_kernel<<<(NN * 32 + 255) / 256, 256>>>(
            gagw, gau, ia, agi, bnin, bnrec, oa[step], gas);

        state_gru_kernel<<<NG, 80>>>(gas, ges, is_, Ws, Us, bsin, bsrec, os[step]);

        ia = oa[step]; ie = oe[step]; is_ = os[step];
    }
}

// round 12
// speedup vs baseline: 1.1545x; 1.1545x over previous
#include <cuda_runtime.h>
#include <math.h>

#define NN 10000
#define NE 40000
#define NG 128
#define VC 1584   // 32*48 kernel cols + 48 bias cols

// ---------------- scratch (static device globals; no runtime alloc) ----------
__device__ float g_a[NN * 32];
__device__ float g_e[NE * 32];
__device__ float g_s[NG * 16];
__device__ float g_v[NN * VC];      // 63.4 MB
__device__ float g_vs[NG * VC];     // per-graph state part of v
__device__ float g_wt[48 * VC];     // transposed kernel+bias
__device__ float g_agg[NN * 48];
__device__ float g_asum[NG * 32];
__device__ float g_esum[NG * 32];
__device__ float g_wcat2[32 * 192]; // [We rows 80:112 | Ue]
__device__ float g_wcat3[32 * 288]; // [We rows 0:32 | We rows 32:64 | Un]
__device__ float g_pau[NN * 288];   // a @ wcat3  (pa cols 0:192, au cols 192:288)
__device__ float g_ew[NE * 192];    // e @ wcat2
__device__ float g_s3[NG * 96];     // s @ We rows 64:80
__device__ float g_agw[NN * 96];    // agg @ Wn

__device__ __forceinline__ float sigm(float x) { return 1.f / (1.f + expf(-x)); }

__device__ __forceinline__ unsigned f2tf(float f) {
    unsigned u;
    asm("cvt.rna.tf32.f32 %0, %1;" : "=r"(u) : "f"(f));
    return u;
}
__device__ __forceinline__ void mma_tf32(float c[4],
                                         unsigned a0, unsigned a1,
                                         unsigned a2, unsigned a3,
                                         unsigned b0, unsigned b1) {
    asm volatile(
        "mma.sync.aligned.m16n8k8.row.col.f32.tf32.tf32.f32 "
        "{%0,%1,%2,%3}, {%4,%5,%6,%7}, {%8,%9}, {%0,%1,%2,%3};"
        : "+f"(c[0]), "+f"(c[1]), "+f"(c[2]), "+f"(c[3])
        : "r"(a0), "r"(a1), "r"(a2), "r"(a3), "r"(b0), "r"(b1));
}

// ---------------- weight prep ------------------------------------------------
__global__ void build_weights_kernel(const float* __restrict__ kern,
                                     const float* __restrict__ bias,
                                     const float* __restrict__ We,
                                     const float* __restrict__ Ue,
                                     const float* __restrict__ Un,
                                     float* __restrict__ wt,
                                     float* __restrict__ wcat2,
                                     float* __restrict__ wcat3) {
    int idx = blockIdx.x * blockDim.x + threadIdx.x;
    if (idx < 48 * VC) {
        int j = idx / VC, ki = idx % VC;
        wt[idx] = (ki < 1536) ? kern[ki * 48 + j] : bias[(ki - 1536) * 48 + j];
    }
    if (idx < 32 * 192) {
        int k = idx / 192, c = idx % 192;
        wcat2[idx] = (c < 96) ? We[(80 + k) * 96 + c] : Ue[k * 96 + (c - 96)];
    }
    if (idx < 32 * 288) {
        int k = idx / 288, c = idx % 288;
        float val;
        if (c < 96)       val = We[k * 96 + c];
        else if (c < 192) val = We[(32 + k) * 96 + (c - 96)];
        else              val = Un[k * 96 + (c - 192)];
        wcat3[idx] = val;
    }
}

// ---------------- zero scratch ------------------------------------------------
__global__ void zero_kernel(float* __restrict__ agg, float* __restrict__ as,
                            float* __restrict__ es) {
    int i = blockIdx.x * blockDim.x + threadIdx.x;
    if (i < NN * 48) agg[i] = 0.f;
    if (i < NG * 32) { as[i] = 0.f; es[i] = 0.f; }
}

// ---------------- small-K dense GEMM: Y(MxNC) = X(MxK) @ W(KxNC) -------------
template<int K, int NC, int RT>
__global__ __launch_bounds__(NC)
void gemm_kernel(const float* __restrict__ X, const float* __restrict__ W,
                 float* __restrict__ Y, int M) {
    __shared__ float sW[K * NC];
    __shared__ __align__(16) float sx[RT * K];
    int tid = threadIdx.x;
    int base = blockIdx.x * RT;
#pragma unroll
    for (int k = 0; k < K; k++) sW[k * NC + tid] = W[k * NC + tid];
    int lim = (M - base) * K;
    for (int i = tid; i < RT * K; i += NC)
        sx[i] = (i < lim) ? X[(size_t)base * K + i] : 0.f;
    __syncthreads();

    float acc[RT];
#pragma unroll
    for (int r = 0; r < RT; r++) acc[r] = 0.f;
    const float4* sx4 = (const float4*)sx;
#pragma unroll
    for (int k4 = 0; k4 < K / 4; k4++) {
        float w0 = sW[(4 * k4 + 0) * NC + tid];
        float w1 = sW[(4 * k4 + 1) * NC + tid];
        float w2 = sW[(4 * k4 + 2) * NC + tid];
        float w3 = sW[(4 * k4 + 3) * NC + tid];
#pragma unroll
        for (int r = 0; r < RT; r++) {
            float4 xv = sx4[r * (K / 4) + k4];
            acc[r] += w0 * xv.x; acc[r] += w1 * xv.y;
            acc[r] += w2 * xv.z; acc[r] += w3 * xv.w;
        }
    }
#pragma unroll
    for (int r = 0; r < RT; r++) {
        int row = base + r;
        if (row < M) Y[(size_t)row * NC + tid] = acc[r];
    }
}

// ---------------- tf32 MMA GEMM: Y(Mx192) = X(Mx32) @ W(32x192) --------------
// 256 thr = 8 warps (4m x 2n); block tile 64x192; smem-staged coalesced stores.
__global__ __launch_bounds__(256)
void gemm_mma_k32_n192(const float* __restrict__ X, const float* __restrict__ W,
                       float* __restrict__ Y, int M) {
    __shared__ __align__(16) char raw[(64 * 33 + 32 * 196) * 4];
    unsigned* sA = (unsigned*)raw;                      // 64*33
    unsigned* sB = (unsigned*)(raw) + 64 * 33;          // 32*196
    float* sC = (float*)raw;                            // 64*100 (reused per half)
    int m0 = blockIdx.x * 64;
    int tid = threadIdx.x;

    for (int i = tid; i < 64 * 32; i += 256) {
        int r = i >> 5, k = i & 31;
        float val = (m0 + r < M) ? X[(size_t)(m0 + r) * 32 + k] : 0.f;
        sA[r * 33 + k] = f2tf(val);
    }
    for (int i = tid; i < 32 * 192; i += 256) {
        int k = i / 192, n = i % 192;
        sB[k * 196 + n] = f2tf(W[k * 192 + n]);
    }
    __syncthreads();

    int wid = tid >> 5, lane = tid & 31;
    int wm = wid & 3, wn = wid >> 2;
    int lq = lane >> 2, lr = lane & 3;

    float c[12][4];
#pragma unroll
    for (int nf = 0; nf < 12; nf++)
#pragma unroll
        for (int i = 0; i < 4; i++) c[nf][i] = 0.f;

#pragma unroll
    for (int ks = 0; ks < 4; ks++) {
        int ar = wm * 16 + lq;
        int ac = ks * 8 + lr;
        unsigned a0 = sA[ar * 33 + ac];
        unsigned a1 = sA[(ar + 8) * 33 + ac];
        unsigned a2 = sA[ar * 33 + ac + 4];
        unsigned a3 = sA[(ar + 8) * 33 + ac + 4];
#pragma unroll
        for (int nf = 0; nf < 12; nf++) {
            int bn = wn * 96 + nf * 8 + lq;
            unsigned b0 = sB[(ks * 8 + lr) * 196 + bn];
            unsigned b1 = sB[(ks * 8 + 4 + lr) * 196 + bn];
            mma_tf32(c[nf], a0, a1, a2, a3, b0, b1);
        }
    }
    __syncthreads();   // done with sA/sB

    int row_l = wm * 16 + lq;
#pragma unroll
    for (int half = 0; half < 2; half++) {
        if (wn == half) {
#pragma unroll
            for (int nf = 0; nf < 12; nf++) {
                int col = nf * 8 + lr * 2;
                *(float2*)&sC[row_l * 100 + col] = make_float2(c[nf][0], c[nf][1]);
                *(float2*)&sC[(row_l + 8) * 100 + col] = make_float2(c[nf][2], c[nf][3]);
            }
        }
        __syncthreads();
        for (int i = tid; i < 64 * 24; i += 256) {
            int r = i / 24, c4 = i % 24;
            int row = m0 + r;
            if (row < M) {
                float4 cv = *(float4*)&sC[r * 100 + c4 * 4];
                *(float4*)&Y[(size_t)row * 192 + half * 96 + c4 * 4] = cv;
            }
        }
        __syncthreads();
    }
}

// ---------------- edge GRU finalize (pure elementwise) -----------------------
__global__ __launch_bounds__(256)
void edge_finalize_kernel(const float* __restrict__ pau,
                          const float* __restrict__ ew,
                          const float* __restrict__ s3,
                          const float* __restrict__ e_in,
                          const int* __restrict__ pair,
                          const int* __restrict__ bgi,
                          const float* __restrict__ bin,
                          const float* __restrict__ brec,
                          float* __restrict__ e_out,
                          float* __restrict__ esum) {
    int idx = blockIdx.x * blockDim.x + threadIdx.x;
    if (idx >= NE * 32) return;
    int e = idx >> 5, j = idx & 31;
    int src = pair[2 * e], dst = pair[2 * e + 1], g = bgi[e];
    const float* pA = pau + (size_t)src * 288;
    const float* pB = pau + (size_t)dst * 288 + 96;
    const float* pS = s3 + g * 96;
    const float* pE = ew + (size_t)e * 192;
    float xz = pA[j]      + pB[j]      + pS[j]      + pE[j]      + bin[j];
    float xr = pA[32 + j] + pB[32 + j] + pS[32 + j] + pE[32 + j] + bin[32 + j];
    float xh = pA[64 + j] + pB[64 + j] + pS[64 + j] + pE[64 + j] + bin[64 + j];
    float hz = pE[96 + j]  + brec[j];
    float hr = pE[128 + j] + brec[32 + j];
    float hh = pE[160 + j] + brec[64 + j];
    float h  = e_in[(size_t)e * 32 + j];
    float z  = sigm(xz + hz);
    float r  = sigm(xr + hr);
    float hc = tanhf(xh + r * hh);
    float val = z * h + (1.f - z) * hc;
    e_out[(size_t)e * 32 + j] = val;
    atomicAdd(&esum[g * 32 + j], val);
}

// ---------------- node GRU finalize ------------------------------------------
__global__ __launch_bounds__(256)
void node_finalize_kernel(const float* __restrict__ agw,
                          const float* __restrict__ pau,
                          const float* __restrict__ a_in,
                          const int* __restrict__ agi,
                          const float* __restrict__ bin,
                          const float* __restrict__ brec,
                          float* __restrict__ a_out,
                          float* __restrict__ asum) {
    int idx = blockIdx.x * blockDim.x + threadIdx.x;
    if (idx >= NN * 32) return;
    int n = idx >> 5, j = idx & 31;
    const float* pX = agw + (size_t)n * 96;
    const float* pH = pau + (size_t)n * 288 + 192;
    float xz = pX[j]      + bin[j];
    float xr = pX[32 + j] + bin[32 + j];
    float xh = pX[64 + j] + bin[64 + j];
    float hz = pH[j]      + brec[j];
    float hr = pH[32 + j] + brec[32 + j];
    float hh = pH[64 + j] + brec[64 + j];
    float h  = a_in[(size_t)n * 32 + j];
    float z  = sigm(xz + hz);
    float r  = sigm(xr + hr);
    float hc = tanhf(xh + r * hh);
    float val = z * h + (1.f - z) * hc;
    a_out[(size_t)n * 32 + j] = val;
    atomicAdd(&asum[agi[n] * 32 + j], val);
}

// ---------------- vs[g][c] = sum_j wt[32+j][c] * s[g][j]  (state part) -------
__global__ __launch_bounds__(256)
void vs_kernel(const float* __restrict__ s, const float* __restrict__ wt,
               float* __restrict__ vs) {
    __shared__ float ss[16];
    int g = blockIdx.y;
    int c = blockIdx.x * 256 + threadIdx.x;
    if (threadIdx.x < 16) ss[threadIdx.x] = s[g * 16 + threadIdx.x];
    __syncthreads();
    if (c >= VC) return;
    float acc = 0.f;
#pragma unroll
    for (int j = 0; j < 16; j++) acc += ss[j] * wt[(32 + j) * VC + c];
    vs[(size_t)g * VC + c] = acc;
}

// ---------------- v = a @ Wt_a (tf32) + vs[agi], smem-staged epilogue --------
__global__ __launch_bounds__(256)
void compute_v_mma_kernel(const float* __restrict__ a,
                          const int* __restrict__ agi,
                          const float* __restrict__ wt,
                          const float* __restrict__ vs,
                          float* __restrict__ v) {
    __shared__ __align__(16) char raw[64 * 132 * 4];   // C stage (33792B) >= A+B
    unsigned* sA = (unsigned*)raw;                     // 64*33
    unsigned* sB = (unsigned*)(raw) + 64 * 33;         // 32*132
    float* sC = (float*)raw;                           // 64*132 (reused)
    __shared__ int s_gi[64];
    int m0 = blockIdx.y * 64;
    int n0 = blockIdx.x * 128;
    int tid = threadIdx.x;

    for (int i = tid; i < 64 * 32; i += 256) {
        int r = i >> 5, k = i & 31;
        float val = (m0 + r < NN) ? a[(size_t)(m0 + r) * 32 + k] : 0.f;
        sA[r * 33 + k] = f2tf(val);
    }
    for (int i = tid; i < 32 * 128; i += 256) {
        int k = i >> 7, n = i & 127;
        float val = (n0 + n < VC) ? wt[(size_t)k * VC + n0 + n] : 0.f;
        sB[k * 132 + n] = f2tf(val);
    }
    if (tid < 64) s_gi[tid] = (m0 + tid < NN) ? agi[m0 + tid] : 0;
    __syncthreads();

    int wid = tid >> 5, lane = tid & 31;
    int wm = wid & 3, wn = wid >> 2;
    int lq = lane >> 2, lr = lane & 3;

    float c[8][4];
#pragma unroll
    for (int nf = 0; nf < 8; nf++)
#pragma unroll
        for (int i = 0; i < 4; i++) c[nf][i] = 0.f;

#pragma unroll
    for (int ks = 0; ks < 4; ks++) {
        int ar = wm * 16 + lq;
        int ac = ks * 8 + lr;
        unsigned a0 = sA[ar * 33 + ac];
        unsigned a1 = sA[(ar + 8) * 33 + ac];
        unsigned a2 = sA[ar * 33 + ac + 4];
        unsigned a3 = sA[(ar + 8) * 33 + ac + 4];
#pragma unroll
        for (int nf = 0; nf < 8; nf++) {
            int bn = wn * 64 + nf * 8 + lq;
            unsigned b0 = sB[(ks * 8 + lr) * 132 + bn];
            unsigned b1 = sB[(ks * 8 + 4 + lr) * 132 + bn];
            mma_tf32(c[nf], a0, a1, a2, a3, b0, b1);
        }
    }
    __syncthreads();   // done with sA/sB

    // stage C fragments into padded smem tile
    int row_l = wm * 16 + lq;
    int cb = wn * 64 + lr * 2;
#pragma unroll
    for (int nf = 0; nf < 8; nf++) {
        int col = cb + nf * 8;
        *(float2*)&sC[row_l * 132 + col] = make_float2(c[nf][0], c[nf][1]);
        *(float2*)&sC[(row_l + 8) * 132 + col] = make_float2(c[nf][2], c[nf][3]);
    }
    __syncthreads();

    // coalesced float4 writeout with vs gather-add
    for (int i = tid; i < 64 * 32; i += 256) {
        int r = i >> 5, c4 = i & 31;
        int row = m0 + r;
        int col = n0 + c4 * 4;
        if (row >= NN || col >= VC) continue;
        float4 cv = *(float4*)&sC[r * 132 + c4 * 4];
        float4 wv = *(const float4*)&vs[(size_t)s_gi[r] * VC + col];
        cv.x += wv.x; cv.y += wv.y; cv.z += wv.z; cv.w += wv.w;
        *(float4*)&v[(size_t)row * VC + col] = cv;
    }
}

// ---------------- per-edge message + scatter-add by src (src-run dedup) ------
#define EPW 8
__global__ __launch_bounds__(256)
void scatter_kernel(const float* __restrict__ e_feat,
                    const int* __restrict__ pair,
                    const float* __restrict__ v,
                    float* __restrict__ agg) {
    int lane = threadIdx.x & 31;
    int warp = (blockIdx.x * blockDim.x + threadIdx.x) >> 5;
    int e0 = warp * EPW;
    if (e0 >= NE) return;
    int eend = min(e0 + EPW, NE);
    int cur_src = __ldg(&pair[2 * e0]);
    float acc0 = 0.f, acc1 = 0.f;
    for (int e = e0; e < eend; e++) {
        int src = __ldg(&pair[2 * e]);
        int dst = __ldg(&pair[2 * e + 1]);
        if (src != cur_src) {
            atomicAdd(&agg[cur_src * 48 + lane], acc0);
            if (lane < 16) atomicAdd(&agg[cur_src * 48 + 32 + lane], acc1);
            acc0 = 0.f; acc1 = 0.f; cur_src = src;
        }
        const float* vp = v + (size_t)dst * VC;
        float ev = __ldg(&e_feat[(size_t)e * 32 + lane]);
        acc0 += __ldg(&vp[1536 + lane]);
        if (lane < 16) acc1 += __ldg(&vp[1568 + lane]);
#pragma unroll
        for (int k = 0; k < 32; k++) {
            float ek = __shfl_sync(0xffffffffu, ev, k);
            acc0 += ek * __ldg(&vp[k * 48 + lane]);
            if (lane < 16) acc1 += ek * __ldg(&vp[k * 48 + 32 + lane]);
        }
    }
    atomicAdd(&agg[cur_src * 48 + lane], acc0);
    if (lane < 16) atomicAdd(&agg[cur_src * 48 + 32 + lane], acc1);
}

// ---------------- state GRU: s = GRU([asum, esum, s], s) ---------------------
__global__ void state_gru_kernel(
    const float* __restrict__ asum, const float* __restrict__ esum,
    const float* __restrict__ s_in,
    const float* __restrict__ Ws, const float* __restrict__ Us,
    const float* __restrict__ bsin, const float* __restrict__ bsrec,
    float* __restrict__ s_out) {
    __shared__ float sx[80];
    __shared__ float shh[16];
    __shared__ float sxw[48];
    __shared__ float shu[48];
    int g = blockIdx.x;
    int c = threadIdx.x;  // 80
    if (c < 32)      sx[c] = asum[g * 32 + c];
    else if (c < 64) sx[c] = esum[g * 32 + (c - 32)];
    else             sx[c] = s_in[g * 16 + (c - 64)];
    if (c < 16) shh[c] = s_in[g * 16 + c];
    __syncthreads();
    if (c < 48) {
        float xw = bsin[c], hu = bsrec[c];
        for (int k = 0; k < 80; k++) xw += sx[k] * Ws[k * 48 + c];
        for (int k = 0; k < 16; k++) hu += shh[k] * Us[k * 48 + c];
        sxw[c] = xw; shu[c] = hu;
    }
    __syncthreads();
    if (c < 16) {
        float z = sigm(sxw[c] + shu[c]);
        float r = sigm(sxw[16 + c] + shu[16 + c]);
        float hc = tanhf(sxw[32 + c] + r * shu[32 + c]);
        s_out[g * 16 + c] = z * shh[c] + (1.f - z) * hc;
    }
}

// ---------------- host orchestration -----------------------------------------
extern "C" void kernel_launch(void* const* d_in, const int* in_sizes, int n_in,
                              void* d_out, int out_size) {
    const float* a0    = (const float*)d_in[0];
    const float* e0    = (const float*)d_in[1];
    const float* s0    = (const float*)d_in[2];
    const int*   pair  = (const int*)d_in[3];
    const int*   agi   = (const int*)d_in[4];
    const int*   bgi   = (const int*)d_in[5];
    const float* kern  = (const float*)d_in[6];
    const float* bias  = (const float*)d_in[7];
    const float* We    = (const float*)d_in[8];
    const float* Ue    = (const float*)d_in[9];
    const float* bein  = (const float*)d_in[10];
    const float* berec = (const float*)d_in[11];
    const float* Wn    = (const float*)d_in[12];
    const float* Un    = (const float*)d_in[13];
    const float* bnin  = (const float*)d_in[14];
    const float* bnrec = (const float*)d_in[15];
    const float* Ws    = (const float*)d_in[16];
    const float* Us    = (const float*)d_in[17];
    const float* bsin  = (const float*)d_in[18];
    const float* bsrec = (const float*)d_in[19];
    float* out = (float*)d_out;

    float *ga, *ge, *gs, *gv, *gvs, *gwt, *gagg, *gas, *ges;
    float *gw2, *gw3, *gpau, *gew, *gs3, *gagw;
    cudaGetSymbolAddress((void**)&ga,    g_a);
    cudaGetSymbolAddress((void**)&ge,    g_e);
    cudaGetSymbolAddress((void**)&gs,    g_s);
    cudaGetSymbolAddress((void**)&gv,    g_v);
    cudaGetSymbolAddress((void**)&gvs,   g_vs);
    cudaGetSymbolAddress((void**)&gwt,   g_wt);
    cudaGetSymbolAddress((void**)&gagg,  g_agg);
    cudaGetSymbolAddress((void**)&gas,   g_asum);
    cudaGetSymbolAddress((void**)&ges,   g_esum);
    cudaGetSymbolAddress((void**)&gw2,   g_wcat2);
    cudaGetSymbolAddress((void**)&gw3,   g_wcat3);
    cudaGetSymbolAddress((void**)&gpau,  g_pau);
    cudaGetSymbolAddress((void**)&gew,   g_ew);
    cudaGetSymbolAddress((void**)&gs3,   g_s3);
    cudaGetSymbolAddress((void**)&gagw,  g_agw);

    static bool s_init = false;
    static cudaStream_t st1, st2;
    static cudaEvent_t ev0[2], evZ[2], evP[2], evE[2];
    if (!s_init) {
        cudaStreamCreateWithFlags(&st1, cudaStreamNonBlocking);
        cudaStreamCreateWithFlags(&st2, cudaStreamNonBlocking);
        for (int i = 0; i < 2; i++) {
            cudaEventCreateWithFlags(&ev0[i], cudaEventDisableTiming);
            cudaEventCreateWithFlags(&evZ[i], cudaEventDisableTiming);
            cudaEventCreateWithFlags(&evP[i], cudaEventDisableTiming);
            cudaEventCreateWithFlags(&evE[i], cudaEventDisableTiming);
        }
        s_init = true;
    }

    build_weights_kernel<<<(48 * VC + 255) / 256, 256>>>(kern, bias, We, Ue, Un,
                                                         gwt, gw2, gw3);

    float* oa[2] = {ga, out};
    float* oe[2] = {ge, out + NN * 32};
    float* os[2] = {gs, out + NN * 32 + NE * 32};
    const float* ia = a0;
    const float* ie = e0;
    const float* is_ = s0;

    for (int step = 0; step < 2; step++) {
        cudaEventRecord(ev0[step], 0);

        // main stream: vs then tf32 v-GEMM with staged epilogue
        vs_kernel<<<dim3((VC + 255) / 256, NG), 256>>>(is_, gwt, gvs);
        compute_v_mma_kernel<<<dim3((VC + 127) / 128, (NN + 63) / 64), 256>>>(
            ia, agi, gwt, gvs, gv);

        // stream 2: zero scratch, fused pa+Un GEMM
        cudaStreamWaitEvent(st2, ev0[step], 0);
        zero_kernel<<<(NN * 48 + 255) / 256, 256, 0, st2>>>(gagg, gas, ges);
        cudaEventRecord(evZ[step], st2);
        gemm_kernel<32, 288, 16><<<NN / 16, 288, 0, st2>>>(ia, gw3, gpau, NN);
        cudaEventRecord(evP[step], st2);

        // stream 1: ew (tf32 MMA, staged epilogue) + s3, then finalize
        cudaStreamWaitEvent(st1, ev0[step], 0);
        gemm_mma_k32_n192<<<NE / 64, 256, 0, st1>>>(ie, gw2, gew, NE);
        gemm_kernel<16, 96, 16><<<NG / 16, 96, 0, st1>>>(is_, We + 64 * 96, gs3, NG);
        cudaStreamWaitEvent(st1, evZ[step], 0);
        cudaStreamWaitEvent(st1, evP[step], 0);
        edge_finalize_kernel<<<(NE * 32 + 255) / 256, 256, 0, st1>>>(
            gpau, gew, gs3, ie, pair, bgi, bein, berec, oe[step], ges);
        cudaEventRecord(evE[step], st1);

        // join on main: scatter needs v (main) + e_out/zeroed agg (st1 chain)
        cudaStreamWaitEvent(0, evE[step], 0);
        scatter_kernel<<<(NE / EPW + 7) / 8, 256>>>(oe[step], pair, gv, gagg);

        gemm_kernel<48, 96, 16><<<NN / 16, 96>>>(gagg, Wn, gagw, NN);
        cudaStreamWaitEvent(0, evP[step], 0);
        node_finalize_kernel<<<(NN * 32 + 255) / 256, 256>>>(
            gagw, gpau, ia, agi, bnin, bnrec, oa[step], gas);

        state_gru_kernel<<<NG, 80>>>(gas, ges, is_, Ws, Us, bsin, bsrec, os[step]);

        ia = oa[step]; ie = oe[step]; is_ = os[step];
    }
}

// round 13
// speedup vs baseline: 1.2446x; 1.0780x over previous
#include <cuda_runtime.h>
#include <math.h>

#define NN 10000
#define NE 40000
#define NG 128
#define VC 1584   // 32*48 kernel cols + 48 bias cols

// ---------------- scratch (static device globals; no runtime alloc) ----------
__device__ float g_a[NN * 32];
__device__ float g_e[NE * 32];
__device__ float g_s[NG * 16];
__device__ float g_v[NN * VC];      // 63.4 MB
__device__ float g_wt[48 * VC];     // transposed kernel+bias
__device__ float g_agg[NN * 48];
__device__ float g_asum[NG * 32];
__device__ float g_esum[NG * 32];
__device__ float g_wcat2[32 * 192]; // [We rows 80:112 | Ue]
__device__ float g_wcat3[32 * 288]; // [We rows 0:32 | We rows 32:64 | Un]
__device__ float g_pau[NN * 288];   // a @ wcat3
__device__ float g_s3[NG * 96];     // s @ We rows 64:80

__device__ __forceinline__ float sigm(float x) { return 1.f / (1.f + expf(-x)); }

__device__ __forceinline__ unsigned f2tf(float f) {
    unsigned u;
    asm("cvt.rna.tf32.f32 %0, %1;" : "=r"(u) : "f"(f));
    return u;
}
__device__ __forceinline__ void mma_tf32(float c[4],
                                         unsigned a0, unsigned a1,
                                         unsigned a2, unsigned a3,
                                         unsigned b0, unsigned b1) {
    asm volatile(
        "mma.sync.aligned.m16n8k8.row.col.f32.tf32.tf32.f32 "
        "{%0,%1,%2,%3}, {%4,%5,%6,%7}, {%8,%9}, {%0,%1,%2,%3};"
        : "+f"(c[0]), "+f"(c[1]), "+f"(c[2]), "+f"(c[3])
        : "r"(a0), "r"(a1), "r"(a2), "r"(a3), "r"(b0), "r"(b1));
}

// ---------------- weight prep ------------------------------------------------
__global__ void build_weights_kernel(const float* __restrict__ kern,
                                     const float* __restrict__ bias,
                                     const float* __restrict__ We,
                                     const float* __restrict__ Ue,
                                     const float* __restrict__ Un,
                                     float* __restrict__ wt,
                                     float* __restrict__ wcat2,
                                     float* __restrict__ wcat3) {
    int idx = blockIdx.x * blockDim.x + threadIdx.x;
    if (idx < 48 * VC) {
        int j = idx / VC, ki = idx % VC;
        wt[idx] = (ki < 1536) ? kern[ki * 48 + j] : bias[(ki - 1536) * 48 + j];
    }
    if (idx < 32 * 192) {
        int k = idx / 192, c = idx % 192;
        wcat2[idx] = (c < 96) ? We[(80 + k) * 96 + c] : Ue[k * 96 + (c - 96)];
    }
    if (idx < 32 * 288) {
        int k = idx / 288, c = idx % 288;
        float val;
        if (c < 96)       val = We[k * 96 + c];
        else if (c < 192) val = We[(32 + k) * 96 + (c - 96)];
        else              val = Un[k * 96 + (c - 192)];
        wcat3[idx] = val;
    }
}

// ---------------- fused v kernel: v = [a | s[agi]] @ wt (tf32, K=48) ---------
// Also zeroes agg. Block tile 64 x 128; 8 warps (4m x 2n).
__global__ __launch_bounds__(256)
void compute_v_fused(const float* __restrict__ a, const float* __restrict__ s,
                     const int* __restrict__ agi, const float* __restrict__ wt,
                     float* __restrict__ v, float* __restrict__ agg) {
    __shared__ __align__(16) char raw[(64 * 52 + 48 * 132) * 4];
    unsigned* sA = (unsigned*)raw;               // 64 x 52 (K=48 padded)
    unsigned* sB = (unsigned*)raw + 64 * 52;     // 48 x 132
    float* sC = (float*)raw;                     // 64 x 132 (reused)
    __shared__ int s_gi[64];
    int m0 = blockIdx.y * 64;
    int n0 = blockIdx.x * 128;
    int tid = threadIdx.x;

    // zero agg chunk (2041 blocks x 236 covers NN*48)
    {
        int bid = blockIdx.y * gridDim.x + blockIdx.x;
        int z = bid * 236 + tid;
        if (tid < 236 && z < NN * 48) agg[z] = 0.f;
    }

    if (tid < 64) s_gi[tid] = (m0 + tid < NN) ? agi[m0 + tid] : 0;
    __syncthreads();

    for (int i = tid; i < 64 * 32; i += 256) {
        int r = i >> 5, k = i & 31;
        float val = (m0 + r < NN) ? a[(size_t)(m0 + r) * 32 + k] : 0.f;
        sA[r * 52 + k] = f2tf(val);
    }
    for (int i = tid; i < 64 * 16; i += 256) {
        int r = i >> 4, k = i & 15;
        float val = (m0 + r < NN) ? s[s_gi[r] * 16 + k] : 0.f;
        sA[r * 52 + 32 + k] = f2tf(val);
    }
    for (int i = tid; i < 48 * 128; i += 256) {
        int k = i >> 7, n = i & 127;
        float val = (n0 + n < VC) ? wt[(size_t)k * VC + n0 + n] : 0.f;
        sB[k * 132 + n] = f2tf(val);
    }
    __syncthreads();

    int wid = tid >> 5, lane = tid & 31;
    int wm = wid & 3, wn = wid >> 2;
    int lq = lane >> 2, lr = lane & 3;

    float c[8][4];
#pragma unroll
    for (int nf = 0; nf < 8; nf++)
#pragma unroll
        for (int i = 0; i < 4; i++) c[nf][i] = 0.f;

#pragma unroll
    for (int ks = 0; ks < 6; ks++) {
        int ar = wm * 16 + lq;
        int ac = ks * 8 + lr;
        unsigned a0 = sA[ar * 52 + ac];
        unsigned a1 = sA[(ar + 8) * 52 + ac];
        unsigned a2 = sA[ar * 52 + ac + 4];
        unsigned a3 = sA[(ar + 8) * 52 + ac + 4];
#pragma unroll
        for (int nf = 0; nf < 8; nf++) {
            int bn = wn * 64 + nf * 8 + lq;
            unsigned b0 = sB[(ks * 8 + lr) * 132 + bn];
            unsigned b1 = sB[(ks * 8 + 4 + lr) * 132 + bn];
            mma_tf32(c[nf], a0, a1, a2, a3, b0, b1);
        }
    }
    __syncthreads();

    int row_l = wm * 16 + lq;
    int cb = wn * 64 + lr * 2;
#pragma unroll
    for (int nf = 0; nf < 8; nf++) {
        int col = cb + nf * 8;
        *(float2*)&sC[row_l * 132 + col] = make_float2(c[nf][0], c[nf][1]);
        *(float2*)&sC[(row_l + 8) * 132 + col] = make_float2(c[nf][2], c[nf][3]);
    }
    __syncthreads();

    for (int i = tid; i < 64 * 32; i += 256) {
        int r = i >> 5, c4 = i & 31;
        int row = m0 + r;
        int col = n0 + c4 * 4;
        if (row >= NN || col >= VC) continue;
        *(float4*)&v[(size_t)row * VC + col] = *(float4*)&sC[r * 132 + c4 * 4];
    }
}

// ---------------- pau GEMM + s3 + zero esum/asum -----------------------------
// blocks 0..624: a @ wcat3 tiles; block 625: s3 = s @ We[64:80]; blocks 0..31
// additionally zero esum/asum.
__global__ __launch_bounds__(288)
void pau_s3_kernel(const float* __restrict__ a, const float* __restrict__ W,
                   const float* __restrict__ Ws3, const float* __restrict__ s,
                   float* __restrict__ pau, float* __restrict__ s3,
                   float* __restrict__ esum, float* __restrict__ asum) {
    __shared__ float sW[32 * 288];
    __shared__ __align__(16) float sx[16 * 32];
    int tid = threadIdx.x;
    int bid = blockIdx.x;

    if (bid < 32 && tid < 256) {
        int z = bid * 256 + tid;
        if (z < NG * 32) esum[z] = 0.f;
        else asum[z - NG * 32] = 0.f;
    }

    if (bid == 625) {
        // s3: tiny GEMM (128x16)@(16x96)
        for (int i = tid; i < NG * 16; i += 288) sW[i] = s[i];
        __syncthreads();
        if (tid < 96) {
            for (int g = 0; g < NG; g++) {
                float acc = 0.f;
#pragma unroll
                for (int k = 0; k < 16; k++) acc += sW[g * 16 + k] * Ws3[k * 96 + tid];
                s3[g * 96 + tid] = acc;
            }
        }
        return;
    }

    int base = bid * 16;
#pragma unroll
    for (int k = 0; k < 32; k++) sW[k * 288 + tid] = W[k * 288 + tid];
    for (int i = tid; i < 16 * 32; i += 288) sx[i] = a[(size_t)base * 32 + i];
    __syncthreads();

    float acc[16];
#pragma unroll
    for (int r = 0; r < 16; r++) acc[r] = 0.f;
    const float4* sx4 = (const float4*)sx;
#pragma unroll
    for (int k4 = 0; k4 < 8; k4++) {
        float w0 = sW[(4 * k4 + 0) * 288 + tid];
        float w1 = sW[(4 * k4 + 1) * 288 + tid];
        float w2 = sW[(4 * k4 + 2) * 288 + tid];
        float w3 = sW[(4 * k4 + 3) * 288 + tid];
#pragma unroll
        for (int r = 0; r < 16; r++) {
            float4 xv = sx4[r * 8 + k4];
            acc[r] += w0 * xv.x; acc[r] += w1 * xv.y;
            acc[r] += w2 * xv.z; acc[r] += w3 * xv.w;
        }
    }
#pragma unroll
    for (int r = 0; r < 16; r++)
        pau[(size_t)(base + r) * 288 + tid] = acc[r];
}

// ---------------- fused edge kernel: ew MMA + GRU finalize -------------------
// Block: 64 edges. Dynamic smem: phase1 sA(64x33)+sB(32x196); phase2 sC(64x196).
__global__ __launch_bounds__(256)
void edge_fused_kernel(const float* __restrict__ e_in,
                       const float* __restrict__ W,
                       const int* __restrict__ pair,
                       const int* __restrict__ bgi,
                       const float* __restrict__ pau,
                       const float* __restrict__ s3,
                       const float* __restrict__ bin,
                       const float* __restrict__ brec,
                       float* __restrict__ e_out,
                       float* __restrict__ esum) {
    extern __shared__ __align__(16) char dynsm[];
    unsigned* sA = (unsigned*)dynsm;               // 64*33
    unsigned* sB = (unsigned*)dynsm + 64 * 33;     // 32*196
    float* sC = (float*)dynsm;                     // 64*196 (reused)
    __shared__ int sSrc[64], sDst[64], sBg[64];
    int m0 = blockIdx.x * 64;
    int tid = threadIdx.x;

    for (int i = tid; i < 64 * 32; i += 256) {
        int r = i >> 5, k = i & 31;
        sA[r * 33 + k] = f2tf(e_in[(size_t)(m0 + r) * 32 + k]);
    }
    for (int i = tid; i < 32 * 192; i += 256) {
        int k = i / 192, n = i % 192;
        sB[k * 196 + n] = f2tf(W[k * 192 + n]);
    }
    if (tid < 64) {
        int e = m0 + tid;
        sSrc[tid] = pair[2 * e];
        sDst[tid] = pair[2 * e + 1];
        sBg[tid]  = bgi[e];
    }
    __syncthreads();

    int wid = tid >> 5, lane = tid & 31;
    int wm = wid & 3, wn = wid >> 2;
    int lq = lane >> 2, lr = lane & 3;

    float c[12][4];
#pragma unroll
    for (int nf = 0; nf < 12; nf++)
#pragma unroll
        for (int i = 0; i < 4; i++) c[nf][i] = 0.f;

#pragma unroll
    for (int ks = 0; ks < 4; ks++) {
        int ar = wm * 16 + lq;
        int ac = ks * 8 + lr;
        unsigned a0 = sA[ar * 33 + ac];
        unsigned a1 = sA[(ar + 8) * 33 + ac];
        unsigned a2 = sA[ar * 33 + ac + 4];
        unsigned a3 = sA[(ar + 8) * 33 + ac + 4];
#pragma unroll
        for (int nf = 0; nf < 12; nf++) {
            int bn = wn * 96 + nf * 8 + lq;
            unsigned b0 = sB[(ks * 8 + lr) * 196 + bn];
            unsigned b1 = sB[(ks * 8 + 4 + lr) * 196 + bn];
            mma_tf32(c[nf], a0, a1, a2, a3, b0, b1);
        }
    }
    __syncthreads();

    int row_l = wm * 16 + lq;
#pragma unroll
    for (int nf = 0; nf < 12; nf++) {
        int col = wn * 96 + nf * 8 + lr * 2;
        *(float2*)&sC[row_l * 196 + col] = make_float2(c[nf][0], c[nf][1]);
        *(float2*)&sC[(row_l + 8) * 196 + col] = make_float2(c[nf][2], c[nf][3]);
    }
    __syncthreads();

    for (int idx = tid; idx < 64 * 32; idx += 256) {
        int el = idx >> 5, j = idx & 31;
        int e = m0 + el;
        int src = sSrc[el], dst = sDst[el], g = sBg[el];
        const float* pA = pau + (size_t)src * 288;
        const float* pB = pau + (size_t)dst * 288 + 96;
        const float* pS = s3 + g * 96;
        const float* pE = sC + el * 196;
        float xz = pA[j]      + pB[j]      + pS[j]      + pE[j]      + bin[j];
        float xr = pA[32 + j] + pB[32 + j] + pS[32 + j] + pE[32 + j] + bin[32 + j];
        float xh = pA[64 + j] + pB[64 + j] + pS[64 + j] + pE[64 + j] + bin[64 + j];
        float hz = pE[96 + j]  + brec[j];
        float hr = pE[128 + j] + brec[32 + j];
        float hh = pE[160 + j] + brec[64 + j];
        float h  = e_in[(size_t)e * 32 + j];
        float z  = sigm(xz + hz);
        float r  = sigm(xr + hr);
        float hc = tanhf(xh + r * hh);
        float val = z * h + (1.f - z) * hc;
        e_out[(size_t)e * 32 + j] = val;
        atomicAdd(&esum[g * 32 + j], val);
    }
}

// ---------------- per-edge message + scatter-add by src (src-run dedup) ------
#define EPW 8
__global__ __launch_bounds__(256)
void scatter_kernel(const float* __restrict__ e_feat,
                    const int* __restrict__ pair,
                    const float* __restrict__ v,
                    float* __restrict__ agg) {
    int lane = threadIdx.x & 31;
    int warp = (blockIdx.x * blockDim.x + threadIdx.x) >> 5;
    int e0 = warp * EPW;
    if (e0 >= NE) return;
    int eend = min(e0 + EPW, NE);
    int cur_src = __ldg(&pair[2 * e0]);
    float acc0 = 0.f, acc1 = 0.f;
    for (int e = e0; e < eend; e++) {
        int src = __ldg(&pair[2 * e]);
        int dst = __ldg(&pair[2 * e + 1]);
        if (src != cur_src) {
            atomicAdd(&agg[cur_src * 48 + lane], acc0);
            if (lane < 16) atomicAdd(&agg[cur_src * 48 + 32 + lane], acc1);
            acc0 = 0.f; acc1 = 0.f; cur_src = src;
        }
        const float* vp = v + (size_t)dst * VC;
        float ev = __ldg(&e_feat[(size_t)e * 32 + lane]);
        acc0 += __ldg(&vp[1536 + lane]);
        if (lane < 16) acc1 += __ldg(&vp[1568 + lane]);
#pragma unroll
        for (int k = 0; k < 32; k++) {
            float ek = __shfl_sync(0xffffffffu, ev, k);
            acc0 += ek * __ldg(&vp[k * 48 + lane]);
            if (lane < 16) acc1 += ek * __ldg(&vp[k * 48 + 32 + lane]);
        }
    }
    atomicAdd(&agg[cur_src * 48 + lane], acc0);
    if (lane < 16) atomicAdd(&agg[cur_src * 48 + 32 + lane], acc1);
}

// ---------------- fused node kernel: agg@Wn GEMM + GRU finalize --------------
__global__ __launch_bounds__(96)
void node_fused_kernel(const float* __restrict__ agg,
                       const float* __restrict__ Wn,
                       const float* __restrict__ pau,
                       const float* __restrict__ a_in,
                       const int* __restrict__ agi,
                       const float* __restrict__ bin,
                       const float* __restrict__ brec,
                       float* __restrict__ a_out,
                       float* __restrict__ asum) {
    __shared__ float sW[48 * 96];
    __shared__ __align__(16) float sx[16 * 48];
    __shared__ float sxw[16 * 96];
    __shared__ int sgi[16];
    int tid = threadIdx.x;
    int base = blockIdx.x * 16;

    for (int i = tid; i < 48 * 96; i += 96) sW[i] = Wn[i];
    for (int i = tid; i < 16 * 48; i += 96) sx[i] = agg[(size_t)base * 48 + i];
    if (tid < 16) sgi[tid] = agi[base + tid];
    __syncthreads();

    float acc[16];
#pragma unroll
    for (int r = 0; r < 16; r++) acc[r] = 0.f;
    const float4* sx4 = (const float4*)sx;
#pragma unroll
    for (int k4 = 0; k4 < 12; k4++) {
        float w0 = sW[(4 * k4 + 0) * 96 + tid];
        float w1 = sW[(4 * k4 + 1) * 96 + tid];
        float w2 = sW[(4 * k4 + 2) * 96 + tid];
        float w3 = sW[(4 * k4 + 3) * 96 + tid];
#pragma unroll
        for (int r = 0; r < 16; r++) {
            float4 xv = sx4[r * 12 + k4];
            acc[r] += w0 * xv.x; acc[r] += w1 * xv.y;
            acc[r] += w2 * xv.z; acc[r] += w3 * xv.w;
        }
    }
#pragma unroll
    for (int r = 0; r < 16; r++) sxw[r * 96 + tid] = acc[r];
    __syncthreads();

    for (int idx = tid; idx < 16 * 32; idx += 96) {
        int nl = idx >> 5, j = idx & 31;
        int n = base + nl;
        const float* pH = pau + (size_t)n * 288 + 192;
        float xz = sxw[nl * 96 + j]      + bin[j];
        float xr = sxw[nl * 96 + 32 + j] + bin[32 + j];
        float xh = sxw[nl * 96 + 64 + j] + bin[64 + j];
        float hz = pH[j]      + brec[j];
        float hr = pH[32 + j] + brec[32 + j];
        float hh = pH[64 + j] + brec[64 + j];
        float h  = a_in[(size_t)n * 32 + j];
        float z  = sigm(xz + hz);
        float r  = sigm(xr + hr);
        float hc = tanhf(xh + r * hh);
        float val = z * h + (1.f - z) * hc;
        a_out[(size_t)n * 32 + j] = val;
        atomicAdd(&asum[sgi[nl] * 32 + j], val);
    }
}

// ---------------- state GRU: s = GRU([asum, esum, s], s) ---------------------
__global__ void state_gru_kernel(
    const float* __restrict__ asum, const float* __restrict__ esum,
    const float* __restrict__ s_in,
    const float* __restrict__ Ws, const float* __restrict__ Us,
    const float* __restrict__ bsin, const float* __restrict__ bsrec,
    float* __restrict__ s_out) {
    __shared__ float sx[80];
    __shared__ float shh[16];
    __shared__ float sxw[48];
    __shared__ float shu[48];
    int g = blockIdx.x;
    int c = threadIdx.x;  // 80
    if (c < 32)      sx[c] = asum[g * 32 + c];
    else if (c < 64) sx[c] = esum[g * 32 + (c - 32)];
    else             sx[c] = s_in[g * 16 + (c - 64)];
    if (c < 16) shh[c] = s_in[g * 16 + c];
    __syncthreads();
    if (c < 48) {
        float xw = bsin[c], hu = bsrec[c];
        for (int k = 0; k < 80; k++) xw += sx[k] * Ws[k * 48 + c];
        for (int k = 0; k < 16; k++) hu += shh[k] * Us[k * 48 + c];
        sxw[c] = xw; shu[c] = hu;
    }
    __syncthreads();
    if (c < 16) {
        float z = sigm(sxw[c] + shu[c]);
        float r = sigm(sxw[16 + c] + shu[16 + c]);
        float hc = tanhf(sxw[32 + c] + r * shu[32 + c]);
        s_out[g * 16 + c] = z * shh[c] + (1.f - z) * hc;
    }
}

// ---------------- host orchestration -----------------------------------------
extern "C" void kernel_launch(void* const* d_in, const int* in_sizes, int n_in,
                              void* d_out, int out_size) {
    const float* a0    = (const float*)d_in[0];
    const float* e0    = (const float*)d_in[1];
    const float* s0    = (const float*)d_in[2];
    const int*   pair  = (const int*)d_in[3];
    const int*   agi   = (const int*)d_in[4];
    const int*   bgi   = (const int*)d_in[5];
    const float* kern  = (const float*)d_in[6];
    const float* bias  = (const float*)d_in[7];
    const float* We    = (const float*)d_in[8];
    const float* Ue    = (const float*)d_in[9];
    const float* bein  = (const float*)d_in[10];
    const float* berec = (const float*)d_in[11];
    const float* Wn    = (const float*)d_in[12];
    const float* Un    = (const float*)d_in[13];
    const float* bnin  = (const float*)d_in[14];
    const float* bnrec = (const float*)d_in[15];
    const float* Ws    = (const float*)d_in[16];
    const float* Us    = (const float*)d_in[17];
    const float* bsin  = (const float*)d_in[18];
    const float* bsrec = (const float*)d_in[19];
    float* out = (float*)d_out;

    float *ga, *ge, *gs, *gv, *gwt, *gagg, *gas, *ges;
    float *gw2, *gw3, *gpau, *gs3;
    cudaGetSymbolAddress((void**)&ga,    g_a);
    cudaGetSymbolAddress((void**)&ge,    g_e);
    cudaGetSymbolAddress((void**)&gs,    g_s);
    cudaGetSymbolAddress((void**)&gv,    g_v);
    cudaGetSymbolAddress((void**)&gwt,   g_wt);
    cudaGetSymbolAddress((void**)&gagg,  g_agg);
    cudaGetSymbolAddress((void**)&gas,   g_asum);
    cudaGetSymbolAddress((void**)&ges,   g_esum);
    cudaGetSymbolAddress((void**)&gw2,   g_wcat2);
    cudaGetSymbolAddress((void**)&gw3,   g_wcat3);
    cudaGetSymbolAddress((void**)&gpau,  g_pau);
    cudaGetSymbolAddress((void**)&gs3,   g_s3);

    static bool s_init = false;
    static cudaStream_t st2;
    static cudaEvent_t ev0[2], evE[2];
    const int EDGE_SMEM = 64 * 196 * 4;   // 50176 bytes
    if (!s_init) {
        cudaStreamCreateWithFlags(&st2, cudaStreamNonBlocking);
        for (int i = 0; i < 2; i++) {
            cudaEventCreateWithFlags(&ev0[i], cudaEventDisableTiming);
            cudaEventCreateWithFlags(&evE[i], cudaEventDisableTiming);
        }
        cudaFuncSetAttribute(edge_fused_kernel,
                             cudaFuncAttributeMaxDynamicSharedMemorySize, EDGE_SMEM);
        s_init = true;
    }

    build_weights_kernel<<<(48 * VC + 255) / 256, 256>>>(kern, bias, We, Ue, Un,
                                                         gwt, gw2, gw3);

    float* oa[2] = {ga, out};
    float* oe[2] = {ge, out + NN * 32};
    float* os[2] = {gs, out + NN * 32 + NE * 32};
    const float* ia = a0;
    const float* ie = e0;
    const float* is_ = s0;

    for (int step = 0; step < 2; step++) {
        cudaEventRecord(ev0[step], 0);

        // main: fused v GEMM (also zeroes agg)
        compute_v_fused<<<dim3((VC + 127) / 128, (NN + 63) / 64), 256>>>(
            ia, is_, agi, gwt, gv, gagg);

        // st2: pau+s3 (+zero esum/asum), then fused edge MMA+GRU
        cudaStreamWaitEvent(st2, ev0[step], 0);
        pau_s3_kernel<<<626, 288, 0, st2>>>(ia, gw3, We + 64 * 96, is_,
                                            gpau, gs3, ges, gas);
        edge_fused_kernel<<<NE / 64, 256, EDGE_SMEM, st2>>>(
            ie, gw2, pair, bgi, gpau, gs3, bein, berec, oe[step], ges);
        cudaEventRecord(evE[step], st2);

        // main: join, scatter, fused node GRU, state GRU
        cudaStreamWaitEvent(0, evE[step], 0);
        scatter_kernel<<<(NE / EPW + 7) / 8, 256>>>(oe[step], pair, gv, gagg);
        node_fused_kernel<<<NN / 16, 96>>>(gagg, Wn, gpau, ia, agi,
                                           bnin, bnrec, oa[step], gas);
        state_gru_kernel<<<NG, 80>>>(gas, ges, is_, Ws, Us, bsin, bsrec, os[step]);

        ia = oa[step]; ie = oe[step]; is_ = os[step];
    }
}